// round 7
// baseline (speedup 1.0000x reference)
#include <cuda_runtime.h>
#include <cstdint>

constexpr int TOK = 32, DMODEL = 256, HEADS = 8, INNER = 512;
constexpr int GROUPS = 4096, NQKV = 1536, DHEAD = 64;
constexpr int NG = 2;                 // groups per block
constexpr int MR = 64;                // rows per block

// ---- smem plan (float offsets) ----
// A-side (LDSM) strides %32==4; B-side (scalar) strides %32==8.
constexpr int XS_STR = 260, XS_OFF = 0;                    // x tf32 [64][256]
constexpr int WS_OFF = XS_OFF + MR * XS_STR;               // W ring: 3 slots x 3200
constexpr int WS_STR = 200;                                //   B1 chunk [16k][192]
constexpr int WO_STR = 264;                                //   B3 chunk [8k][256]
constexpr int WSLOT  = 3200;
constexpr int PS_STR = 36,  PS_OFF = WS_OFF + 2 * WSLOT;   // P [64][36] (alias slot2)
constexpr int QS_STR = 68,  QS_OFF = WS_OFF + 3 * WSLOT;   // Q tf32 [64][64]
constexpr int KS_STR = 68,  KS_OFF = QS_OFF + MR * QS_STR;
constexpr int VS_STR = 72,  VS_OFF = KS_OFF + MR * KS_STR;
constexpr int AS_STR = 68,  AS_OFF = VS_OFF + MR * VS_STR;
constexpr int SM_FLOATS = AS_OFF + MR * AS_STR;            // 43904 floats
constexpr int SM_BYTES  = SM_FLOATS * 4;                   // ~171.5 KB -> 1 block/SM

__device__ __forceinline__ float ftf(float f) {
    uint32_t u; asm("cvt.rna.tf32.f32 %0, %1;" : "=r"(u) : "f"(f));
    return __uint_as_float(u);
}
__device__ __forceinline__ uint32_t ftfu(float f) {
    uint32_t u; asm("cvt.rna.tf32.f32 %0, %1;" : "=r"(u) : "f"(f));
    return u;
}
__device__ __forceinline__ void mma8(float* d, const uint32_t* a, const uint32_t* b) {
    asm volatile("mma.sync.aligned.m16n8k8.row.col.f32.tf32.tf32.f32 "
                 "{%0,%1,%2,%3},{%4,%5,%6,%7},{%8,%9},{%0,%1,%2,%3};"
                 : "+f"(d[0]), "+f"(d[1]), "+f"(d[2]), "+f"(d[3])
                 : "r"(a[0]), "r"(a[1]), "r"(a[2]), "r"(a[3]), "r"(b[0]), "r"(b[1]));
}
__device__ __forceinline__ void ldsm4(uint32_t* r, uint32_t saddr) {
    asm volatile("ldmatrix.sync.aligned.m8n8.x4.shared.b16 {%0,%1,%2,%3}, [%4];"
                 : "=r"(r[0]), "=r"(r[1]), "=r"(r[2]), "=r"(r[3]) : "r"(saddr));
}
__device__ __forceinline__ void cpa16(uint32_t dst, const void* src) {
    asm volatile("cp.async.ca.shared.global [%0], [%1], 16;" :: "r"(dst), "l"(src));
}
__device__ __forceinline__ void cp_commit() { asm volatile("cp.async.commit_group;"); }
template<int N> __device__ __forceinline__ void cp_wait() {
    asm volatile("cp.async.wait_group %0;" :: "n"(N));
}

__global__ __launch_bounds__(256, 1)
void fused_attn_kernel(const float* __restrict__ x,
                       const float* __restrict__ Wqkv,
                       const float* __restrict__ Wout,
                       const float* __restrict__ bout,
                       float* __restrict__ out)
{
    extern __shared__ float sm[];
    const int tid = threadIdx.x;
    const int blk = blockIdx.x;       // handles rows blk*64 .. +63 (2 groups)
    const int w   = tid >> 5;
    const int ln  = tid & 31;
    const int g4  = ln >> 2;
    const int t4  = ln & 3;

    const uint32_t sb = (uint32_t)__cvta_generic_to_shared(sm);
    const int lrow = ln & 15, lcol4 = (ln >> 4) * 4;
    const uint32_t xs_lds = sb + ((XS_OFF + lrow * XS_STR + lcol4) << 2);
    const uint32_t qs_lds = sb + ((QS_OFF + ((w >> 2) * 16 + lrow) * QS_STR + lcol4) << 2);
    const uint32_t ps_lds = sb + ((PS_OFF + lrow * PS_STR + lcol4) << 2);
    const uint32_t as_lds = sb + ((AS_OFF + lrow * AS_STR + lcol4) << 2);

    // staging index precompute
    int wkk[3], wcol[3];
    #pragma unroll
    for (int it = 0; it < 3; it++) {
        int l = tid + it * 256;
        wkk[it] = l / 48; wcol[it] = (l % 48) * 4;
    }
    int odd8[2], oc4[2];
    #pragma unroll
    for (int it = 0; it < 2; it++) {
        int l = tid + it * 256;
        odd8[it] = l >> 6; oc4[it] = (l & 63) * 4;
    }
    auto issueW = [&](int h, int c, int p) {
        const int kc = c * 16;
        #pragma unroll
        for (int it = 0; it < 3; it++) {
            const int col = wcol[it], sec = col >> 6, dd = col & 63;
            cpa16(sb + ((WS_OFF + p * WSLOT + wkk[it] * WS_STR + col) << 2),
                  Wqkv + (size_t)(kc + wkk[it]) * NQKV + sec * INNER + h * DHEAD + dd);
        }
        cp_commit();
    };
    auto issueWO = [&](int h, int c, int p) {
        const int dc = c * 8;
        #pragma unroll
        for (int it = 0; it < 2; it++) {
            cpa16(sb + ((WS_OFF + p * WSLOT + odd8[it] * WO_STR + oc4[it]) << 2),
                  Wout + (size_t)(h * DHEAD + dc + odd8[it]) * DMODEL + oc4[it]);
        }
        cp_commit();
    };

    issueW(0, 0, 0); issueW(0, 1, 1);   // 2 chunks in flight

    // stage x[64][256] as tf32
    {
        const float4* xg = reinterpret_cast<const float4*>(x + (size_t)blk * MR * DMODEL);
        #pragma unroll
        for (int it = 0; it < 16; it++) {
            int l = tid + it * 256;
            int row = l >> 6, c4 = l & 63;
            float4 v = xg[l];
            *reinterpret_cast<float4*>(sm + XS_OFF + row * XS_STR + c4 * 4) =
                make_float4(ftf(v.x), ftf(v.y), ftf(v.z), ftf(v.w));
        }
    }
    // out accumulators [mt 0..3][nt 0..3], bias preloaded
    float o[4][4][4];
    #pragma unroll
    for (int nt = 0; nt < 4; nt++) {
        float b0 = bout[w * 32 + nt * 8 + 2 * t4];
        float b1 = bout[w * 32 + nt * 8 + 2 * t4 + 1];
        #pragma unroll
        for (int mt = 0; mt < 4; mt++) {
            o[mt][nt][0] = b0; o[mt][nt][1] = b1;
            o[mt][nt][2] = b0; o[mt][nt][3] = b1;
        }
    }

    for (int h = 0; h < HEADS; h++) {
        // ===== B1: QKV, M=64. Warp w owns qkv cols [w*8, w*8+8) =====
        float d1[3][4][4] = {};
        #pragma unroll 1
        for (int c = 0; c < 16; c++) {
            if (c < 14) { issueW(h, c + 2, (c + 2) % 3); cp_wait<2>(); }
            else if (c == 14) cp_wait<1>();
            else cp_wait<0>();
            __syncthreads();
            const float* wb = sm + WS_OFF + (c % 3) * WSLOT;
            const int kc = c * 16;
            #pragma unroll
            for (int ks = 0; ks < 2; ks++) {
                uint32_t a[4][4];
                #pragma unroll
                for (int mt = 0; mt < 4; mt++)
                    ldsm4(a[mt], xs_lds + ((mt * 16 * XS_STR + kc + ks * 8) << 2));
                const float* wr = wb + ks * 8 * WS_STR + (w << 3) + g4;
                #pragma unroll
                for (int m = 0; m < 3; m++) {
                    const float* wc = wr + m * 64;
                    uint32_t b[2] = { ftfu(wc[t4 * WS_STR]), ftfu(wc[(t4 + 4) * WS_STR]) };
                    #pragma unroll
                    for (int mt = 0; mt < 4; mt++) mma8(d1[m][mt], a[mt], b);
                }
            }
            __syncthreads();
        }
        // write Q/K/V (tf32), 64 rows
        {
            const int cc = w * 8 + 2 * t4;
            #pragma unroll
            for (int m = 0; m < 3; m++) {
                float* dst = sm + (m == 0 ? QS_OFF : m == 1 ? KS_OFF : VS_OFF);
                const int str = (m == 2) ? VS_STR : QS_STR;
                #pragma unroll
                for (int mt = 0; mt < 4; mt++) {
                    int r0 = mt * 16 + g4;
                    dst[r0 * str + cc]           = ftf(d1[m][mt][0]);
                    dst[r0 * str + cc + 1]       = ftf(d1[m][mt][1]);
                    dst[(r0 + 8) * str + cc]     = ftf(d1[m][mt][2]);
                    dst[(r0 + 8) * str + cc + 1] = ftf(d1[m][mt][3]);
                }
            }
        }
        __syncthreads();

        // ===== B2a: S = Q K^T per group. Warp w -> tile (mt=w>>2, nt=w&3) =====
        {
            const int mt = w >> 2, nt = w & 3;
            #pragma unroll
            for (int grp = 0; grp < NG; grp++) {
                float s[4] = {};
                #pragma unroll
                for (int ks = 0; ks < 8; ks++) {
                    uint32_t a[4];
                    ldsm4(a, qs_lds + ((grp * 32 * QS_STR + ks * 8) << 2));
                    const float* kb = sm + KS_OFF + (grp * 32 + nt * 8 + g4) * KS_STR + ks * 8;
                    uint32_t b[2] = { __float_as_uint(kb[t4]), __float_as_uint(kb[t4 + 4]) };
                    mma8(s, a, b);
                }
                const int r0 = grp * 32 + mt * 16 + g4, cc = nt * 8 + 2 * t4;
                sm[PS_OFF + r0 * PS_STR + cc]           = s[0] * 0.125f;
                sm[PS_OFF + r0 * PS_STR + cc + 1]       = s[1] * 0.125f;
                sm[PS_OFF + (r0 + 8) * PS_STR + cc]     = s[2] * 0.125f;
                sm[PS_OFF + (r0 + 8) * PS_STR + cc + 1] = s[3] * 0.125f;
            }
        }
        __syncthreads();

        // ===== B2b: softmax, 64 rows, 4 threads/row (8 cols each) =====
        {
            const int i = tid >> 2, cb = tid & 3;
            float sv[8];
            #pragma unroll
            for (int jj = 0; jj < 8; jj++) sv[jj] = sm[PS_OFF + i * PS_STR + cb + jj * 4];
            float mx = sv[0];
            #pragma unroll
            for (int jj = 1; jj < 8; jj++) mx = fmaxf(mx, sv[jj]);
            #pragma unroll
            for (int msk = 1; msk < 4; msk <<= 1)
                mx = fmaxf(mx, __shfl_xor_sync(0xffffffffu, mx, msk));
            float sum = 0.f;
            #pragma unroll
            for (int jj = 0; jj < 8; jj++) { sv[jj] = __expf(sv[jj] - mx); sum += sv[jj]; }
            #pragma unroll
            for (int msk = 1; msk < 4; msk <<= 1)
                sum += __shfl_xor_sync(0xffffffffu, sum, msk);
            const float inv = 1.f / sum;
            #pragma unroll
            for (int jj = 0; jj < 8; jj++)
                sm[PS_OFF + i * PS_STR + cb + jj * 4] = ftf(sv[jj] * inv);
        }
        __syncthreads();
        issueWO(h, 0, 0); issueWO(h, 1, 1);   // prefetch Wout during B2c

        // ===== B2c: A = P V per group. Warp w owns d-cols [w*8, w*8+8) =====
        {
            #pragma unroll
            for (int grp = 0; grp < NG; grp++) {
                float dpv[2][4] = {};
                #pragma unroll
                for (int ks = 0; ks < 4; ks++) {
                    const float* vb = sm + VS_OFF + (grp * 32 + ks * 8) * VS_STR + (w << 3) + g4;
                    uint32_t b[2] = { __float_as_uint(vb[t4 * VS_STR]),
                                      __float_as_uint(vb[(t4 + 4) * VS_STR]) };
                    uint32_t a0[4], a1[4];
                    ldsm4(a0, ps_lds + ((grp * 32 * PS_STR + ks * 8) << 2));
                    ldsm4(a1, ps_lds + (((grp * 32 + 16) * PS_STR + ks * 8) << 2));
                    mma8(dpv[0], a0, b);
                    mma8(dpv[1], a1, b);
                }
                const int cc = w * 8 + 2 * t4;
                #pragma unroll
                for (int half = 0; half < 2; half++) {
                    int r0 = grp * 32 + half * 16 + g4;
                    sm[AS_OFF + r0 * AS_STR + cc]           = ftf(dpv[half][0]);
                    sm[AS_OFF + r0 * AS_STR + cc + 1]       = ftf(dpv[half][1]);
                    sm[AS_OFF + (r0 + 8) * AS_STR + cc]     = ftf(dpv[half][2]);
                    sm[AS_OFF + (r0 + 8) * AS_STR + cc + 1] = ftf(dpv[half][3]);
                }
            }
        }
        __syncthreads();

        // ===== B3: out += A_h @ Wout[h*64:(h+1)*64]. M=64, warp w: n [w*32,+32) =====
        #pragma unroll 1
        for (int c = 0; c < 8; c++) {
            if (c < 6) { issueWO(h, c + 2, (c + 2) % 3); cp_wait<2>(); }
            else if (c == 6) cp_wait<1>();
            else cp_wait<0>();
            __syncthreads();
            const int dc = c * 8;
            uint32_t a[4][4];
            #pragma unroll
            for (int mt = 0; mt < 4; mt++)
                ldsm4(a[mt], as_lds + ((mt * 16 * AS_STR + dc) << 2));
            const float* wo = sm + WS_OFF + (c % 3) * WSLOT + (w << 5) + g4;
            #pragma unroll
            for (int nt = 0; nt < 4; nt++) {
                const float* wc = wo + nt * 8;
                uint32_t b[2] = { ftfu(wc[t4 * WO_STR]), ftfu(wc[(t4 + 4) * WO_STR]) };
                #pragma unroll
                for (int mt = 0; mt < 4; mt++) mma8(o[mt][nt], a[mt], b);
            }
            __syncthreads();
        }
        if (h < 7) { issueW(h + 1, 0, 0); issueW(h + 1, 1, 1); }
    }

    // ---- store: rows blk*64 + mt*16 + g4 (+8), cols w*32 + nt*8 + 2*t4 ----
    #pragma unroll
    for (int mt = 0; mt < 4; mt++)
        #pragma unroll
        for (int nt = 0; nt < 4; nt++) {
            const int r0 = mt * 16 + g4, cc = w * 32 + nt * 8 + 2 * t4;
            float* p0 = out + ((size_t)blk * MR + r0) * DMODEL + cc;
            float* p1 = out + ((size_t)blk * MR + r0 + 8) * DMODEL + cc;
            *reinterpret_cast<float2*>(p0) = make_float2(o[mt][nt][0], o[mt][nt][1]);
            *reinterpret_cast<float2*>(p1) = make_float2(o[mt][nt][2], o[mt][nt][3]);
        }
}

extern "C" void kernel_launch(void* const* d_in, const int* in_sizes, int n_in,
                              void* d_out, int out_size)
{
    const float* x    = (const float*)d_in[0];   // [4,1024,32,256]
    const float* Wqkv = (const float*)d_in[1];   // [256,1536]
    const float* Wout = (const float*)d_in[2];   // [512,256]
    const float* bout = (const float*)d_in[3];   // [256]
    float* out = (float*)d_out;                  // [131072,256]

    cudaFuncSetAttribute(fused_attn_kernel,
                         cudaFuncAttributeMaxDynamicSharedMemorySize, SM_BYTES);
    fused_attn_kernel<<<GROUPS / NG, 256, SM_BYTES>>>(x, Wqkv, Wout, bout, out);
}